// round 1
// baseline (speedup 1.0000x reference)
#include <cuda_runtime.h>

// Problem constants (fixed by the dataset)
#define NODES_MAX 50000
#define FIN 256
#define FE  64
#define FOUT 256

// ---------------------------------------------------------------------------
// Scratch (allocation-free rule: __device__ globals)
// ---------------------------------------------------------------------------
__device__ float g_agg_h[(size_t)NODES_MAX * FIN];  // 51.2 MB
__device__ float g_agg_e[(size_t)NODES_MAX * FE];   // 12.8 MB
__device__ int   g_outd[NODES_MAX];
__device__ int   g_ind[NODES_MAX];
__device__ float g_norm_out[NODES_MAX];
__device__ float g_norm_in[NODES_MAX];

// ---------------------------------------------------------------------------
// Zero scratch each replay (graph replays reuse module state)
// ---------------------------------------------------------------------------
__global__ void zero_kernel(int N) {
    int stride = gridDim.x * blockDim.x;
    int i = blockIdx.x * blockDim.x + threadIdx.x;
    float4 z = make_float4(0.f, 0.f, 0.f, 0.f);
    int nh4 = N * (FIN / 4);
    int ne4 = N * (FE / 4);
    for (int j = i; j < nh4; j += stride) ((float4*)g_agg_h)[j] = z;
    for (int j = i; j < ne4; j += stride) ((float4*)g_agg_e)[j] = z;
    for (int j = i; j < N; j += stride) { g_outd[j] = 0; g_ind[j] = 0; }
}

// ---------------------------------------------------------------------------
// Degree histograms
// ---------------------------------------------------------------------------
__global__ void deg_kernel(const int* __restrict__ src,
                           const int* __restrict__ dst, int E) {
    int e = blockIdx.x * blockDim.x + threadIdx.x;
    if (e < E) {
        atomicAdd(&g_outd[src[e]], 1);
        atomicAdd(&g_ind[dst[e]], 1);
    }
}

__global__ void norm_kernel(int N) {
    int n = blockIdx.x * blockDim.x + threadIdx.x;
    if (n < N) {
        g_norm_out[n] = rsqrtf((float)max(g_outd[n], 1));
        g_norm_in[n]  = rsqrtf((float)max(g_ind[n], 1));
    }
}

// ---------------------------------------------------------------------------
// Edge scatter: agg_h[dst] += feat[src]*norm_out[src]; agg_e[dst] += edge_feat
// 64 threads per edge, float4 lanes, vectorized reductions (red.global.v4.f32)
// ---------------------------------------------------------------------------
__device__ __forceinline__ void red4(float* addr, float4 v) {
    asm volatile("red.global.add.v4.f32 [%0], {%1, %2, %3, %4};"
                 :: "l"(addr), "f"(v.x), "f"(v.y), "f"(v.z), "f"(v.w)
                 : "memory");
}

__global__ void scatter_kernel(const float* __restrict__ feat,
                               const float* __restrict__ edge_feat,
                               const int* __restrict__ src,
                               const int* __restrict__ dst, int E) {
    long long t = (long long)blockIdx.x * blockDim.x + threadIdx.x;
    int e = (int)(t >> 6);
    int l = (int)(t & 63);
    if (e >= E) return;
    int s = __ldg(src + e);
    int d = __ldg(dst + e);
    float ns = g_norm_out[s];
    float4 v = __ldg((const float4*)feat + (size_t)s * (FIN / 4) + l);
    v.x *= ns; v.y *= ns; v.z *= ns; v.w *= ns;
    red4(g_agg_h + (size_t)d * FIN + l * 4, v);
    if (l < FE / 4) {
        float4 ev = __ldg((const float4*)edge_feat + (size_t)e * (FE / 4) + l);
        red4(g_agg_e + (size_t)d * FE + l * 4, ev);
    }
}

// ---------------------------------------------------------------------------
// SGEMM: out[M,256] = [agg_h | agg_e] (M x 320) @ W (320 x 256)
// epilogue: * norm_in[row] + bias, relu
// 128x128 tile, BK=16, 256 threads, 8x8 microtile
// ---------------------------------------------------------------------------
#define BM 128
#define BN 128
#define BK 16

__global__ __launch_bounds__(256, 2)
void gemm_kernel(const float* __restrict__ W,
                 const float* __restrict__ bias,
                 float* __restrict__ out, int M) {
    __shared__ float As[BK][BM + 1];   // +1 pad: conflict-free transpose stores
    __shared__ float Bs[BK][BN];

    int tid = threadIdx.x;
    int tx = tid & 15;
    int ty = tid >> 4;
    int row0 = blockIdx.y * BM;
    int col0 = blockIdx.x * BN;

    float acc[8][8];
#pragma unroll
    for (int i = 0; i < 8; i++)
#pragma unroll
        for (int j = 0; j < 8; j++) acc[i][j] = 0.f;

    const int KT = (FIN + FE) / BK;  // 20
    for (int kt = 0; kt < KT; kt++) {
        // A tile: 128 rows x 16 k (512 float4), transposed into As[k][m]
#pragma unroll
        for (int i = 0; i < 2; i++) {
            int idx = tid + i * 256;
            int r = idx >> 2;       // 0..127
            int kq = idx & 3;       // float4 within 16-k chunk
            int rg = row0 + r;
            float4 v = make_float4(0.f, 0.f, 0.f, 0.f);
            if (rg < M) {
                const float* p = (kt < FIN / BK)
                    ? (g_agg_h + (size_t)rg * FIN + kt * BK + kq * 4)
                    : (g_agg_e + (size_t)rg * FE + (kt - FIN / BK) * BK + kq * 4);
                v = *(const float4*)p;
            }
            As[kq * 4 + 0][r] = v.x;
            As[kq * 4 + 1][r] = v.y;
            As[kq * 4 + 2][r] = v.z;
            As[kq * 4 + 3][r] = v.w;
        }
        // B tile: 16 k x 128 cols (512 float4)
#pragma unroll
        for (int i = 0; i < 2; i++) {
            int idx = tid + i * 256;
            int kk = idx >> 5;      // 0..15
            int c4 = idx & 31;      // 0..31
            int kg = kt * BK + kk;
            float4 v = *(const float4*)(W + (size_t)kg * FOUT + col0 + c4 * 4);
            *(float4*)&Bs[kk][c4 * 4] = v;
        }
        __syncthreads();

#pragma unroll
        for (int kk = 0; kk < BK; kk++) {
            float a[8], b[8];
#pragma unroll
            for (int i = 0; i < 8; i++) a[i] = As[kk][ty * 8 + i];
#pragma unroll
            for (int j = 0; j < 8; j++) b[j] = Bs[kk][tx * 8 + j];
#pragma unroll
            for (int i = 0; i < 8; i++)
#pragma unroll
                for (int j = 0; j < 8; j++)
                    acc[i][j] = fmaf(a[i], b[j], acc[i][j]);
        }
        __syncthreads();
    }

#pragma unroll
    for (int i = 0; i < 8; i++) {
        int row = row0 + ty * 8 + i;
        if (row >= M) continue;
        float ni = g_norm_in[row];
#pragma unroll
        for (int j = 0; j < 8; j += 4) {
            int col = col0 + tx * 8 + j;
            float4 o;
            o.x = fmaxf(fmaf(acc[i][j + 0], ni, bias[col + 0]), 0.f);
            o.y = fmaxf(fmaf(acc[i][j + 1], ni, bias[col + 1]), 0.f);
            o.z = fmaxf(fmaf(acc[i][j + 2], ni, bias[col + 2]), 0.f);
            o.w = fmaxf(fmaf(acc[i][j + 3], ni, bias[col + 3]), 0.f);
            *(float4*)&out[(size_t)row * FOUT + col] = o;
        }
    }
}

// ---------------------------------------------------------------------------
// Launch (graph-capturable: kernel launches only, default stream)
// ---------------------------------------------------------------------------
extern "C" void kernel_launch(void* const* d_in, const int* in_sizes, int n_in,
                              void* d_out, int out_size) {
    const float* feat      = (const float*)d_in[0];
    const float* edge_feat = (const float*)d_in[1];
    const float* weight    = (const float*)d_in[2];
    const float* bias      = (const float*)d_in[3];
    const int*   src       = (const int*)d_in[4];
    const int*   dst       = (const int*)d_in[5];
    float* out = (float*)d_out;

    int N = in_sizes[0] / FIN;   // 50000
    int E = in_sizes[4];         // 800000

    zero_kernel<<<4096, 256>>>(N);
    deg_kernel<<<(E + 255) / 256, 256>>>(src, dst, E);
    norm_kernel<<<(N + 255) / 256, 256>>>(N);

    long long total = (long long)E * 64;
    int sblocks = (int)((total + 255) / 256);
    scatter_kernel<<<sblocks, 256>>>(feat, edge_feat, src, dst, E);

    dim3 ggrid(FOUT / BN, (N + BM - 1) / BM);
    gemm_kernel<<<ggrid, 256>>>(weight, bias, out, N);
}

// round 6
// speedup vs baseline: 1.2457x; 1.2457x over previous
#include <cuda_runtime.h>

#define NODES_MAX 50000
#define EDGES_MAX 800000
#define FIN 256
#define FE  64
#define FTOT 320
#define FOUT 256

// ---------------------------------------------------------------------------
// Scratch (__device__ globals; allocation-free rule)
// ---------------------------------------------------------------------------
__device__ float g_agg[(size_t)NODES_MAX * FTOT];      // 64 MB: [agg_h | agg_e]
__device__ int   g_outd[NODES_MAX];
__device__ int   g_ind[NODES_MAX];
__device__ int   g_cursor[NODES_MAX];
__device__ float g_norm_out[NODES_MAX];
__device__ float g_norm_in[NODES_MAX];
__device__ int   g_rowstart[NODES_MAX + 1];
__device__ int   g_bsum[256];
__device__ int2  g_csr[EDGES_MAX];                     // {src, edge_id} grouped by dst

// ---------------------------------------------------------------------------
__global__ void zero_kernel(int N) {
    int i = blockIdx.x * blockDim.x + threadIdx.x;
    if (i < N) { g_outd[i] = 0; g_ind[i] = 0; g_cursor[i] = 0; }
}

__global__ void deg_kernel(const int* __restrict__ src,
                           const int* __restrict__ dst, int E) {
    int e = blockIdx.x * blockDim.x + threadIdx.x;
    if (e < E) {
        atomicAdd(&g_outd[src[e]], 1);
        atomicAdd(&g_ind[dst[e]], 1);
    }
}

__global__ void norm_kernel(int N) {
    int n = blockIdx.x * blockDim.x + threadIdx.x;
    if (n < N) {
        g_norm_out[n] = rsqrtf((float)max(g_outd[n], 1));
        g_norm_in[n]  = rsqrtf((float)max(g_ind[n], 1));
    }
}

// ---- exclusive scan of g_ind -> g_rowstart (3 kernels, 512-elt blocks) ----
__global__ void scanA_kernel(int N) {
    __shared__ int sm[512];
    int t = threadIdx.x;
    int i = blockIdx.x * 512 + t;
    int v = (i < N) ? g_ind[i] : 0;
    sm[t] = v;
    __syncthreads();
#pragma unroll
    for (int off = 1; off < 512; off <<= 1) {
        int x = (t >= off) ? sm[t - off] : 0;
        __syncthreads();
        sm[t] += x;
        __syncthreads();
    }
    if (i <= N) g_rowstart[i] = sm[t] - v;   // exclusive (within block)
    if (t == 511) g_bsum[blockIdx.x] = sm[511];
}

__global__ void scanB_kernel(int nblocks) {
    if (threadIdx.x == 0) {
        int run = 0;
        for (int b = 0; b < nblocks; b++) { int x = g_bsum[b]; g_bsum[b] = run; run += x; }
    }
}

__global__ void scanC_kernel(int N, int E) {
    int i = blockIdx.x * 512 + threadIdx.x;
    if (i < N) g_rowstart[i] += g_bsum[blockIdx.x];
    if (i == N) g_rowstart[N] = E;
}

// ---- fill CSR grouped by dst ----
__global__ void fill_kernel(const int* __restrict__ src,
                            const int* __restrict__ dst, int E) {
    int e = blockIdx.x * blockDim.x + threadIdx.x;
    if (e < E) {
        int d = dst[e];
        int pos = g_rowstart[d] + atomicAdd(&g_cursor[d], 1);
        g_csr[pos] = make_int2(src[e], e);
    }
}

// ---------------------------------------------------------------------------
// Gather aggregation: one 64-lane group per dst node, 4 nodes per 256-thr block
// agg[d, :256] = sum feat[src]*norm_out[src];  agg[d, 256:320] = sum edge_feat
// ---------------------------------------------------------------------------
__global__ __launch_bounds__(256)
void agg_kernel(const float4* __restrict__ feat4,
                const float4* __restrict__ edge4, int N, int E) {
    int node = blockIdx.x * 4 + (threadIdx.x >> 6);
    int lane = threadIdx.x & 63;
    if (node >= N) return;
    int beg = g_rowstart[node];
    int end = g_rowstart[node + 1];

    float4 acc  = make_float4(0.f, 0.f, 0.f, 0.f);
    float4 acce = make_float4(0.f, 0.f, 0.f, 0.f);

    if (beg < end) {
        int2 nxt = __ldg(&g_csr[beg]);
        for (int i = beg; i < end; i++) {
            int2 cur = nxt;
            if (i + 1 < end) nxt = __ldg(&g_csr[i + 1]);
            float ns = g_norm_out[cur.x];
            float4 v = __ldg(feat4 + (size_t)cur.x * (FIN / 4) + lane);
            acc.x = fmaf(v.x, ns, acc.x);
            acc.y = fmaf(v.y, ns, acc.y);
            acc.z = fmaf(v.z, ns, acc.z);
            acc.w = fmaf(v.w, ns, acc.w);
            if (lane < FE / 4) {
                float4 ev = __ldg(edge4 + (size_t)cur.y * (FE / 4) + lane);
                acce.x += ev.x; acce.y += ev.y; acce.z += ev.z; acce.w += ev.w;
            }
        }
    }
    float4* row = (float4*)g_agg + (size_t)node * (FTOT / 4);
    row[lane] = acc;
    if (lane < FE / 4) row[FIN / 4 + lane] = acce;
}

// ---------------------------------------------------------------------------
// SGEMM: out[M,256] = agg (M x 320) @ W (320 x 256); epi: *norm_in + bias, relu
// 128x128x16 tiles, 256 threads, 8x8 microtile, register-prefetch pipeline
// ---------------------------------------------------------------------------
#define BM 128
#define BN 128
#define BK 16

__global__ __launch_bounds__(256, 2)
void gemm_kernel(const float* __restrict__ W,
                 const float* __restrict__ bias,
                 float* __restrict__ out, int M) {
    __shared__ float As[BK][BM + 1];
    __shared__ float Bs[BK][BN];

    int tid = threadIdx.x;
    int tx = tid & 15;
    int ty = tid >> 4;
    int row0 = blockIdx.y * BM;
    int col0 = blockIdx.x * BN;

    float acc[8][8];
#pragma unroll
    for (int i = 0; i < 8; i++)
#pragma unroll
        for (int j = 0; j < 8; j++) acc[i][j] = 0.f;

    // prefetch registers
    float4 pa[2], pb[2];
    int ar[2], akq[2], bk[2], bc4[2];
#pragma unroll
    for (int i = 0; i < 2; i++) {
        int idx = tid + i * 256;
        ar[i] = idx >> 2; akq[i] = idx & 3;
        bk[i] = idx >> 5; bc4[i] = idx & 31;
    }

    const int KT = FTOT / BK;  // 20

    // load tile 0
#pragma unroll
    for (int i = 0; i < 2; i++) {
        int rg = row0 + ar[i];
        pa[i] = (rg < M) ? *(const float4*)(g_agg + (size_t)rg * FTOT + akq[i] * 4)
                         : make_float4(0.f, 0.f, 0.f, 0.f);
        pb[i] = *(const float4*)(W + (size_t)bk[i] * FOUT + col0 + bc4[i] * 4);
    }

    for (int kt = 0; kt < KT; kt++) {
        // store prefetched tile to smem
#pragma unroll
        for (int i = 0; i < 2; i++) {
            As[akq[i] * 4 + 0][ar[i]] = pa[i].x;
            As[akq[i] * 4 + 1][ar[i]] = pa[i].y;
            As[akq[i] * 4 + 2][ar[i]] = pa[i].z;
            As[akq[i] * 4 + 3][ar[i]] = pa[i].w;
            *(float4*)&Bs[bk[i]][bc4[i] * 4] = pb[i];
        }
        __syncthreads();

        // prefetch next tile
        if (kt + 1 < KT) {
            int koff = (kt + 1) * BK;
#pragma unroll
            for (int i = 0; i < 2; i++) {
                int rg = row0 + ar[i];
                pa[i] = (rg < M)
                    ? *(const float4*)(g_agg + (size_t)rg * FTOT + koff + akq[i] * 4)
                    : make_float4(0.f, 0.f, 0.f, 0.f);
                pb[i] = *(const float4*)(W + (size_t)(koff + bk[i]) * FOUT + col0 + bc4[i] * 4);
            }
        }

#pragma unroll
        for (int kk = 0; kk < BK; kk++) {
            float a[8], b[8];
#pragma unroll
            for (int i = 0; i < 8; i++) a[i] = As[kk][ty * 8 + i];
#pragma unroll
            for (int j = 0; j < 8; j++) b[j] = Bs[kk][tx * 8 + j];
#pragma unroll
            for (int i = 0; i < 8; i++)
#pragma unroll
                for (int j = 0; j < 8; j++)
                    acc[i][j] = fmaf(a[i], b[j], acc[i][j]);
        }
        __syncthreads();
    }

#pragma unroll
    for (int i = 0; i < 8; i++) {
        int row = row0 + ty * 8 + i;
        if (row >= M) continue;
        float ni = g_norm_in[row];
#pragma unroll
        for (int j = 0; j < 8; j += 4) {
            int col = col0 + tx * 8 + j;
            float4 o;
            o.x = fmaxf(fmaf(acc[i][j + 0], ni, bias[col + 0]), 0.f);
            o.y = fmaxf(fmaf(acc[i][j + 1], ni, bias[col + 1]), 0.f);
            o.z = fmaxf(fmaf(acc[i][j + 2], ni, bias[col + 2]), 0.f);
            o.w = fmaxf(fmaf(acc[i][j + 3], ni, bias[col + 3]), 0.f);
            *(float4*)&out[(size_t)row * FOUT + col] = o;
        }
    }
}

// ---------------------------------------------------------------------------
extern "C" void kernel_launch(void* const* d_in, const int* in_sizes, int n_in,
                              void* d_out, int out_size) {
    const float* feat      = (const float*)d_in[0];
    const float* edge_feat = (const float*)d_in[1];
    const float* weight    = (const float*)d_in[2];
    const float* bias      = (const float*)d_in[3];
    const int*   src       = (const int*)d_in[4];
    const int*   dst       = (const int*)d_in[5];
    float* out = (float*)d_out;

    int N = in_sizes[0] / FIN;   // 50000
    int E = in_sizes[4];         // 800000

    int scan_blocks = (N + 512) / 512;  // cover index N too (rowstart has N+1 slots)

    zero_kernel<<<(N + 255) / 256, 256>>>(N);
    deg_kernel<<<(E + 255) / 256, 256>>>(src, dst, E);
    norm_kernel<<<(N + 255) / 256, 256>>>(N);
    scanA_kernel<<<scan_blocks, 512>>>(N);
    scanB_kernel<<<1, 32>>>(scan_blocks);
    scanC_kernel<<<scan_blocks, 512>>>(N, E);
    fill_kernel<<<(E + 255) / 256, 256>>>(src, dst, E);

    agg_kernel<<<(N + 3) / 4, 256>>>((const float4*)feat, (const float4*)edge_feat, N, E);

    dim3 ggrid(FOUT / BN, (N + BM - 1) / BM);
    gemm_kernel<<<ggrid, 256>>>(weight, bias, out, N);
}

// round 8
// speedup vs baseline: 1.7916x; 1.4382x over previous
#include <cuda_runtime.h>
#include <cuda_bf16.h>
#include <cstdint>

#define NODES_MAX 50000
#define EDGES_MAX 800000
#define FIN 256
#define FE  64
#define FTOT 320
#define FOUT 256

// ---------------------------------------------------------------------------
// Scratch (__device__ globals; allocation-free rule)
// ---------------------------------------------------------------------------
__device__ __nv_bfloat16 g_agg_hi[(size_t)NODES_MAX * FTOT];  // 32 MB
__device__ __nv_bfloat16 g_agg_lo[(size_t)NODES_MAX * FTOT];  // 32 MB
__device__ __nv_bfloat16 g_wt_hi[(size_t)FOUT * FTOT];        // W^T [N,K]
__device__ __nv_bfloat16 g_wt_lo[(size_t)FOUT * FTOT];
__device__ int   g_outd[NODES_MAX];
__device__ int   g_ind[NODES_MAX];
__device__ int   g_cursor[NODES_MAX];
__device__ float g_norm_out[NODES_MAX];
__device__ float g_norm_in[NODES_MAX];
__device__ int   g_rowstart[NODES_MAX + 1];
__device__ int   g_bsum[256];
__device__ int2  g_csr[EDGES_MAX];

// ---------------------------------------------------------------------------
__global__ void zero_kernel(int N) {
    int i = blockIdx.x * blockDim.x + threadIdx.x;
    if (i < N) { g_outd[i] = 0; g_ind[i] = 0; g_cursor[i] = 0; }
}

__global__ void deg_kernel(const int* __restrict__ src,
                           const int* __restrict__ dst, int E) {
    int e = blockIdx.x * blockDim.x + threadIdx.x;
    if (e < E) {
        atomicAdd(&g_outd[src[e]], 1);
        atomicAdd(&g_ind[dst[e]], 1);
    }
}

__global__ void norm_kernel(int N) {
    int n = blockIdx.x * blockDim.x + threadIdx.x;
    if (n < N) {
        g_norm_out[n] = rsqrtf((float)max(g_outd[n], 1));
        g_norm_in[n]  = rsqrtf((float)max(g_ind[n], 1));
    }
}

// W [320,256] row-major -> Wt [256,320] bf16 hi/lo
__global__ void wsplit_kernel(const float* __restrict__ W) {
    int idx = blockIdx.x * blockDim.x + threadIdx.x;
    if (idx < FTOT * FOUT) {
        int k = idx >> 8;      // /256
        int n = idx & 255;
        float w = W[idx];
        __nv_bfloat16 h = __float2bfloat16(w);
        __nv_bfloat16 l = __float2bfloat16(w - __bfloat162float(h));
        g_wt_hi[(size_t)n * FTOT + k] = h;
        g_wt_lo[(size_t)n * FTOT + k] = l;
    }
}

// ---- exclusive scan of g_ind -> g_rowstart ----
__global__ void scanA_kernel(int N) {
    __shared__ int sm[512];
    int t = threadIdx.x;
    int i = blockIdx.x * 512 + t;
    int v = (i < N) ? g_ind[i] : 0;
    sm[t] = v;
    __syncthreads();
#pragma unroll
    for (int off = 1; off < 512; off <<= 1) {
        int x = (t >= off) ? sm[t - off] : 0;
        __syncthreads();
        sm[t] += x;
        __syncthreads();
    }
    if (i <= N) g_rowstart[i] = sm[t] - v;
    if (t == 511) g_bsum[blockIdx.x] = sm[511];
}

__global__ void scanB_kernel(int nblocks) {
    if (threadIdx.x == 0) {
        int run = 0;
        for (int b = 0; b < nblocks; b++) { int x = g_bsum[b]; g_bsum[b] = run; run += x; }
    }
}

__global__ void scanC_kernel(int N, int E) {
    int i = blockIdx.x * 512 + threadIdx.x;
    if (i < N) g_rowstart[i] += g_bsum[blockIdx.x];
    if (i == N) g_rowstart[N] = E;
}

__global__ void fill_kernel(const int* __restrict__ src,
                            const int* __restrict__ dst, int E) {
    int e = blockIdx.x * blockDim.x + threadIdx.x;
    if (e < E) {
        int d = dst[e];
        int pos = g_rowstart[d] + atomicAdd(&g_cursor[d], 1);
        g_csr[pos] = make_int2(src[e], e);
    }
}

// ---------------------------------------------------------------------------
// Gather aggregation -> bf16 hi/lo rows of [agg_h | agg_e]
// ---------------------------------------------------------------------------
__device__ __forceinline__ void split_store2(__nv_bfloat16* hi, __nv_bfloat16* lo,
                                             float a, float b) {
    __nv_bfloat16 ha = __float2bfloat16(a), hb = __float2bfloat16(b);
    __nv_bfloat16 la = __float2bfloat16(a - __bfloat162float(ha));
    __nv_bfloat16 lb = __float2bfloat16(b - __bfloat162float(hb));
    *(__nv_bfloat162*)hi = __nv_bfloat162(ha, hb);
    *(__nv_bfloat162*)lo = __nv_bfloat162(la, lb);
}

__global__ __launch_bounds__(256)
void agg_kernel(const float4* __restrict__ feat4,
                const float4* __restrict__ edge4, int N, int E) {
    int node = blockIdx.x * 4 + (threadIdx.x >> 6);
    int lane = threadIdx.x & 63;
    if (node >= N) return;
    int beg = g_rowstart[node];
    int end = g_rowstart[node + 1];

    float4 acc  = make_float4(0.f, 0.f, 0.f, 0.f);
    float4 acce = make_float4(0.f, 0.f, 0.f, 0.f);

    if (beg < end) {
        int2 nxt = __ldg(&g_csr[beg]);
        for (int i = beg; i < end; i++) {
            int2 cur = nxt;
            if (i + 1 < end) nxt = __ldg(&g_csr[i + 1]);
            float ns = g_norm_out[cur.x];
            float4 v = __ldg(feat4 + (size_t)cur.x * (FIN / 4) + lane);
            acc.x = fmaf(v.x, ns, acc.x);
            acc.y = fmaf(v.y, ns, acc.y);
            acc.z = fmaf(v.z, ns, acc.z);
            acc.w = fmaf(v.w, ns, acc.w);
            if (lane < FE / 4) {
                float4 ev = __ldg(edge4 + (size_t)cur.y * (FE / 4) + lane);
                acce.x += ev.x; acce.y += ev.y; acce.z += ev.z; acce.w += ev.w;
            }
        }
    }
    __nv_bfloat16* rh = g_agg_hi + (size_t)node * FTOT;
    __nv_bfloat16* rl = g_agg_lo + (size_t)node * FTOT;
    split_store2(rh + lane * 4,     rl + lane * 4,     acc.x, acc.y);
    split_store2(rh + lane * 4 + 2, rl + lane * 4 + 2, acc.z, acc.w);
    if (lane < FE / 4) {
        split_store2(rh + FIN + lane * 4,     rl + FIN + lane * 4,     acce.x, acce.y);
        split_store2(rh + FIN + lane * 4 + 2, rl + FIN + lane * 4 + 2, acce.z, acce.w);
    }
}

// ---------------------------------------------------------------------------
// Tensor-core GEMM via mma.sync (baseline PTX, bf16 3-pass split):
//   out[128-tile, 128-tile] = agg(hi,lo) [M,320] @ Wt(hi,lo)^T [256,320]
// CTA: 256 thr = 8 warps (2m x 4n); warp tile 64x32; K-chunks of 32.
// Epilogue: *norm_in[row] + bias[col], relu.
// ---------------------------------------------------------------------------
#define KC 32
#define AST 40   // smem row stride (bf16 units): conflict-free frag loads

__device__ __forceinline__ void mma16816(float* c, const uint32_t* a, const uint32_t* b) {
    asm volatile("mma.sync.aligned.m16n8k16.row.col.f32.bf16.bf16.f32 "
        "{%0,%1,%2,%3}, {%4,%5,%6,%7}, {%8,%9}, {%0,%1,%2,%3};"
        : "+f"(c[0]), "+f"(c[1]), "+f"(c[2]), "+f"(c[3])
        : "r"(a[0]), "r"(a[1]), "r"(a[2]), "r"(a[3]), "r"(b[0]), "r"(b[1]));
}

__global__ __launch_bounds__(256)
void gemm_mma_kernel(const float* __restrict__ bias,
                     float* __restrict__ out, int M) {
    __shared__ __nv_bfloat16 Ah[128 * AST], Al[128 * AST];
    __shared__ __nv_bfloat16 Bh[128 * AST], Bl[128 * AST];

    int tid = threadIdx.x;
    int wid = tid >> 5, lid = tid & 31;
    int row0 = blockIdx.y * 128;
    int col0 = blockIdx.x * 128;
    int wm = (wid >> 2) * 64;      // warp m offset: 0/64
    int wn = (wid & 3) * 32;       // warp n offset: 0/32/64/96
    int qr = lid >> 2;             // 0..7
    int qc = (lid & 3) * 2;        // 0,2,4,6

    float acc[4][4][4];
#pragma unroll
    for (int mf = 0; mf < 4; mf++)
#pragma unroll
        for (int nf = 0; nf < 4; nf++)
#pragma unroll
            for (int q = 0; q < 4; q++) acc[mf][nf][q] = 0.f;

    // gmem->smem tile indexing: idx = tid + i*256; r = idx>>2 (0..127), u = idx&3
    int r_ = tid >> 2, u_ = tid & 3;
    const int NCH = FTOT / KC;   // 10

    uint4 pah[2], pal[2], pbh[2], pbl[2];
    uint4 z4 = make_uint4(0, 0, 0, 0);

#define LOAD_CHUNK(c)                                                          \
    {                                                                          \
        _Pragma("unroll")                                                      \
        for (int i = 0; i < 2; i++) {                                          \
            int r = r_ + i * 64;                                               \
            int rg = row0 + r;                                                 \
            size_t go = (size_t)rg * FTOT + (c) * KC + u_ * 8;                 \
            if (rg < M) {                                                      \
                pah[i] = *(const uint4*)(g_agg_hi + go);                       \
                pal[i] = *(const uint4*)(g_agg_lo + go);                       \
            } else { pah[i] = z4; pal[i] = z4; }                               \
            size_t gw = (size_t)(col0 + r) * FTOT + (c) * KC + u_ * 8;         \
            pbh[i] = *(const uint4*)(g_wt_hi + gw);                            \
            pbl[i] = *(const uint4*)(g_wt_lo + gw);                            \
        }                                                                      \
    }

    LOAD_CHUNK(0);

    for (int c = 0; c < NCH; c++) {
        // store prefetched tiles
#pragma unroll
        for (int i = 0; i < 2; i++) {
            int r = r_ + i * 64;
            int so = r * AST + u_ * 8;
            *(uint4*)&Ah[so] = pah[i];
            *(uint4*)&Al[so] = pal[i];
            *(uint4*)&Bh[so] = pbh[i];
            *(uint4*)&Bl[so] = pbl[i];
        }
        __syncthreads();

        if (c + 1 < NCH) LOAD_CHUNK(c + 1);

#pragma unroll
        for (int ko = 0; ko < KC; ko += 16) {
            // B fragments for the 4 n-frags (hi & lo): each reg is one LDS.32
            uint32_t bh[4][2], bl[4][2];
#pragma unroll
            for (int nf = 0; nf < 4; nf++) {
                int nrow = wn + nf * 8 + qr;
                bh[nf][0] = *(const uint32_t*)&Bh[nrow * AST + ko + qc];
                bh[nf][1] = *(const uint32_t*)&Bh[nrow * AST + ko + qc + 8];
                bl[nf][0] = *(const uint32_t*)&Bl[nrow * AST + ko + qc];
                bl[nf][1] = *(const uint32_t*)&Bl[nrow * AST + ko + qc + 8];
            }
#pragma unroll
            for (int mf = 0; mf < 4; mf++) {
                int mrow = wm + mf * 16 + qr;
                uint32_t ah[4], al[4];
                ah[0] = *(const uint32_t*)&Ah[mrow * AST + ko + qc];
                ah[1] = *(const uint32_t*)&Ah[(mrow + 8) * AST + ko + qc];
                ah[2] = *(const uint32_t*)&Ah[mrow * AST + ko + qc + 8];
                ah[3] = *(const uint32_t*)&Ah[(mrow + 8) * AST + ko + qc + 8];
                al[0] = *(const uint32_t*)&Al[mrow * AST + ko + qc];
                al[1] = *(const uint32_t*)&Al[(mrow + 8) * AST + ko + qc];
                al[2] = *(const uint32_t*)&Al[mrow * AST + ko + qc + 8];
                al[3] = *(const uint32_t*)&Al[(mrow + 8) * AST + ko + qc + 8];
#pragma unroll
                for (int nf = 0; nf < 4; nf++) {
                    mma16816(acc[mf][nf], ah, bh[nf]);   // Ah*Bh
                    mma16816(acc[mf][nf], ah, bl[nf]);   // Ah*Bl
                    mma16816(acc[mf][nf], al, bh[nf]);   // Al*Bh
                }
            }
        }
        __syncthreads();
    }

    // Epilogue: c0/c1 -> (row=qr, col=qc..qc+1); c2/c3 -> (row=qr+8)
#pragma unroll
    for (int mf = 0; mf < 4; mf++) {
        int ra = row0 + wm + mf * 16 + qr;
        int rb = ra + 8;
        float na = (ra < M) ? g_norm_in[ra] : 0.f;
        float nb = (rb < M) ? g_norm_in[rb] : 0.f;
#pragma unroll
        for (int nf = 0; nf < 4; nf++) {
            int col = col0 + wn + nf * 8 + qc;
            float b0 = __ldg(bias + col), b1 = __ldg(bias + col + 1);
            if (ra < M) {
                float2 o;
                o.x = fmaxf(fmaf(acc[mf][nf][0], na, b0), 0.f);
                o.y = fmaxf(fmaf(acc[mf][nf][1], na, b1), 0.f);
                *(float2*)&out[(size_t)ra * FOUT + col] = o;
            }
            if (rb < M) {
                float2 o;
                o.x = fmaxf(fmaf(acc[mf][nf][2], nb, b0), 0.f);
                o.y = fmaxf(fmaf(acc[mf][nf][3], nb, b1), 0.f);
                *(float2*)&out[(size_t)rb * FOUT + col] = o;
            }
        }
    }
}

// ---------------------------------------------------------------------------
extern "C" void kernel_launch(void* const* d_in, const int* in_sizes, int n_in,
                              void* d_out, int out_size) {
    const float* feat      = (const float*)d_in[0];
    const float* edge_feat = (const float*)d_in[1];
    const float* weight    = (const float*)d_in[2];
    const float* bias      = (const float*)d_in[3];
    const int*   src       = (const int*)d_in[4];
    const int*   dst       = (const int*)d_in[5];
    float* out = (float*)d_out;

    int N = in_sizes[0] / FIN;   // 50000
    int E = in_sizes[4];         // 800000

    int scan_blocks = (N + 512) / 512;

    zero_kernel<<<(N + 255) / 256, 256>>>(N);
    deg_kernel<<<(E + 255) / 256, 256>>>(src, dst, E);
    norm_kernel<<<(N + 255) / 256, 256>>>(N);
    scanA_kernel<<<scan_blocks, 512>>>(N);
    scanB_kernel<<<1, 32>>>(scan_blocks);
    scanC_kernel<<<scan_blocks, 512>>>(N, E);
    fill_kernel<<<(E + 255) / 256, 256>>>(src, dst, E);
    wsplit_kernel<<<(FTOT * FOUT + 255) / 256, 256>>>(weight);

    agg_kernel<<<(N + 3) / 4, 256>>>((const float4*)feat, (const float4*)edge_feat, N, E);

    dim3 ggrid(FOUT / 128, (N + 127) / 128);
    gemm_mma_kernel<<<ggrid, 256>>>(bias, out, N);
}